// round 4
// baseline (speedup 1.0000x reference)
#include <cuda_runtime.h>
#include <cstdint>

#define GRIDL 256
#define CELLS (130 * 256 * 256)   // coords reach 129 = 127 + tap 2
#define NMAX  262144

__device__ int g_head[CELLS];
__device__ int g_next[NMAX];

__global__ void init_head() {
    int stride = gridDim.x * blockDim.x;
    for (int i = blockIdx.x * blockDim.x + threadIdx.x; i < CELLS; i += stride)
        g_head[i] = 0;
}

__global__ void build_chains(const int* __restrict__ in_pos, int N) {
    int n = blockIdx.x * blockDim.x + threadIdx.x;
    if (n >= N) return;
    int x = in_pos[3 * n + 0];
    int y = in_pos[3 * n + 1];
    int z = in_pos[3 * n + 2];
    int lid = (x * GRIDL + y) * GRIDL + z;
    int old = atomicExch(&g_head[lid], n + 1);
    g_next[n] = old;
}

// Shared layout: WT (all 27 taps, transposed, padded) then per-warp acc tiles
#define WT_STRIDE 36
#define WT_TAP    (32 * WT_STRIDE)          // 1152 floats per tap
#define SM_WT     (27 * WT_TAP)             // 31104 floats
#define SM_ACC    (16 * 1024)               // 16 warps x 32 rows x 32 f
#define SMEM_BYTES ((SM_WT + SM_ACC) * 4)   // 189952 bytes

__device__ __forceinline__ unsigned long long pack2(float lo, float hi) {
    float2 t = make_float2(lo, hi);
    return *reinterpret_cast<unsigned long long*>(&t);
}

// 16 channels worth: v[0..3] are 4x16B (8 f32x2), wp points at 8 weight pairs
__device__ __forceinline__ void fma4(unsigned long long& a2,
                                     const ulonglong2* v,
                                     const unsigned long long* wp) {
    #pragma unroll
    for (int i = 0; i < 4; i++) {
        asm("fma.rn.f32x2 %0, %1, %2, %0;" : "+l"(a2) : "l"(v[i].x), "l"(wp[2 * i + 0]));
        asm("fma.rn.f32x2 %0, %1, %2, %0;" : "+l"(a2) : "l"(v[i].y), "l"(wp[2 * i + 1]));
    }
}

__device__ __forceinline__ void load4(ulonglong2* v, const ulonglong2* p) {
    #pragma unroll
    for (int i = 0; i < 4; i++) v[i] = __ldg(p + i);
}

__global__ __launch_bounds__(512)
void gather_conv(const float* __restrict__ feat,
                 const int*   __restrict__ out_pos,
                 const float* __restrict__ W,
                 float*       __restrict__ out,
                 int M) {
    extern __shared__ float sm[];
    float* WT  = sm;
    float* acc = sm + SM_WT;

    int tid  = threadIdx.x;
    int warp = tid >> 5;
    int lane = tid & 31;

    // Stage all 27 taps of W transposed+padded: WT[k][f*36+c] = W[k][c][f]
    for (int i = tid; i < 27 * 1024; i += 512) {
        int k = i >> 10;
        int rem = i & 1023;
        int c = rem >> 5;
        int f = rem & 31;
        WT[k * WT_TAP + f * WT_STRIDE + c] = W[i];
    }

    float* accW = acc + warp * 1024;   // [32 rows][32 f]
    #pragma unroll
    for (int r = 0; r < 32; r++) accW[r * 32 + lane] = 0.0f;
    __syncthreads();

    int rowBase = blockIdx.x * 512 + warp * 32;
    int myRow = rowBase + lane;
    bool valid = myRow < M;
    int myLid = 0;
    if (valid) {
        int x = out_pos[3 * myRow + 0];
        int y = out_pos[3 * myRow + 1];
        int z = out_pos[3 * myRow + 2];
        myLid = (x * GRIDL + y) * GRIDL + z;
    }

    const ulonglong2* featv = (const ulonglong2*)feat;   // 8 x 16B per point

    // prefetch head for tap 0
    int hcur = valid ? __ldg(&g_head[myLid]) : 0;   // tap 0 offset = 0

    for (int k = 0; k < 27; k++) {
        int hnext = 0;
        if (k < 26) {
            int k1 = k + 1;
            int di = k1 / 9, rem = k1 - di * 9, dj = rem / 3, dk = rem - dj * 3;
            int off = di * (GRIDL * GRIDL) + dj * GRIDL + dk;
            hnext = valid ? __ldg(&g_head[myLid + off]) : 0;
        }

        unsigned mask = __ballot_sync(0xffffffffu, hcur != 0);
        if (mask) {
            // hoist tap-k weight column (this lane's feature) as 16 f32x2 regs
            unsigned long long w[16];
            const ulonglong2* wrow =
                (const ulonglong2*)(WT + k * WT_TAP + lane * WT_STRIDE);
            #pragma unroll
            for (int i = 0; i < 8; i++) {
                ulonglong2 t = wrow[i];
                w[2 * i + 0] = t.x;
                w[2 * i + 1] = t.y;
            }

            int r0 = __ffs(mask) - 1; mask &= mask - 1;
            int p0 = __shfl_sync(0xffffffffu, hcur, r0) - 1;

            while (1) {
                int r1 = -1, p1 = 0;
                if (mask) {
                    r1 = __ffs(mask) - 1; mask &= mask - 1;
                    p1 = __shfl_sync(0xffffffffu, hcur, r1) - 1;
                }

                const ulonglong2* fp0 = featv + (size_t)p0 * 8;
                const ulonglong2* fp1 = featv + (size_t)p1 * 8;

                // issue first-half loads for both pairs (MLP), plus next ptrs
                ulonglong2 u0[4], u1[4];
                load4(u0, fp0);
                int pn0 = __ldg(&g_next[p0]);
                if (r1 >= 0) load4(u1, fp1);
                int pn1 = (r1 >= 0) ? __ldg(&g_next[p1]) : 0;

                unsigned long long a0 = pack2(accW[r0 * 32 + lane], 0.0f);
                unsigned long long a1 = (r1 >= 0) ? pack2(accW[r1 * 32 + lane], 0.0f) : 0ull;

                fma4(a0, u0, w + 0);          // pair0 chans 0..15
                load4(u0, fp0 + 4);           // reload chans 16..31
                if (r1 >= 0) {
                    fma4(a1, u1, w + 0);      // pair1 chans 0..15
                    load4(u1, fp1 + 4);
                }
                fma4(a0, u0, w + 8);          // pair0 chans 16..31
                while (pn0) {                  // rare duplicate-position chain
                    int n = pn0 - 1;
                    const ulonglong2* fn = featv + (size_t)n * 8;
                    ulonglong2 t[4];
                    load4(t, fn);      fma4(a0, t, w + 0);
                    load4(t, fn + 4);  fma4(a0, t, w + 8);
                    pn0 = __ldg(&g_next[n]);
                }
                {
                    float2 rr = *reinterpret_cast<float2*>(&a0);
                    accW[r0 * 32 + lane] = rr.x + rr.y;
                }

                if (r1 < 0) break;
                fma4(a1, u1, w + 8);          // pair1 chans 16..31
                while (pn1) {
                    int n = pn1 - 1;
                    const ulonglong2* fn = featv + (size_t)n * 8;
                    ulonglong2 t[4];
                    load4(t, fn);      fma4(a1, t, w + 0);
                    load4(t, fn + 4);  fma4(a1, t, w + 8);
                    pn1 = __ldg(&g_next[n]);
                }
                {
                    float2 rr = *reinterpret_cast<float2*>(&a1);
                    accW[r1 * 32 + lane] = rr.x + rr.y;
                }

                if (!mask) break;
                r0 = __ffs(mask) - 1; mask &= mask - 1;
                p0 = __shfl_sync(0xffffffffu, hcur, r0) - 1;
            }
        }
        hcur = hnext;
    }

    // write results (coalesced: 128B per row)
    #pragma unroll
    for (int r = 0; r < 32; r++) {
        int row = rowBase + r;
        if (row < M) out[row * 32 + lane] = accW[r * 32 + lane];
    }
}

extern "C" void kernel_launch(void* const* d_in, const int* in_sizes, int n_in,
                              void* d_out, int out_size) {
    const float* feat    = (const float*)d_in[0];
    const int*   in_pos  = (const int*)d_in[1];
    const int*   out_pos = (const int*)d_in[2];
    const float* W       = (const float*)d_in[3];
    float* out = (float*)d_out;

    int N = in_sizes[0] / 32;
    int M = in_sizes[2] / 3;

    cudaFuncSetAttribute(gather_conv, cudaFuncAttributeMaxDynamicSharedMemorySize, SMEM_BYTES);

    init_head<<<4096, 256>>>();
    build_chains<<<(N + 255) / 256, 256>>>(in_pos, N);
    gather_conv<<<(M + 511) / 512, 512, SMEM_BYTES>>>(feat, out_pos, W, out, M);
}

// round 5
// speedup vs baseline: 1.1814x; 1.1814x over previous
#include <cuda_runtime.h>
#include <cstdint>

#define GRIDL 256
#define CELLS (130 * 256 * 256)   // coords reach 129 = 127 + tap 2
#define NMAX  262144

// Dense voxel grid: head[cell] = point_index+1 (0 = empty), chained via g_next
__device__ int g_head[CELLS];
__device__ int g_next[NMAX];

__global__ void init_head() {
    int stride = gridDim.x * blockDim.x;
    for (int i = blockIdx.x * blockDim.x + threadIdx.x; i < CELLS; i += stride)
        g_head[i] = 0;
}

__global__ void build_chains(const int* __restrict__ in_pos, int N) {
    int n = blockIdx.x * blockDim.x + threadIdx.x;
    if (n >= N) return;
    int x = in_pos[3 * n + 0];
    int y = in_pos[3 * n + 1];
    int z = in_pos[3 * n + 2];
    int lid = (x * GRIDL + y) * GRIDL + z;
    int old = atomicExch(&g_head[lid], n + 1);
    g_next[n] = old;
}

// Shared layout: WT (transposed, padded) 27*32*36 floats, then per-warp acc 16*32*32
#define WT_STRIDE 36
#define WT_TAP    (32 * WT_STRIDE)          // 1152 floats per tap
#define SM_WT     (27 * WT_TAP)             // 31104 floats
#define SM_ACC    (16 * 1024)               // 16384 floats
#define SMEM_BYTES ((SM_WT + SM_ACC) * 4)   // 189952 bytes

union F4U2 { float4 f; ulonglong2 u; };

__device__ __forceinline__ unsigned long long pack2(float lo, float hi) {
    float2 t = make_float2(lo, hi);
    return *reinterpret_cast<unsigned long long*>(&t);
}

__global__ __launch_bounds__(512, 1)
void gather_conv(const float* __restrict__ feat,
                 const int*   __restrict__ out_pos,
                 const float* __restrict__ W,
                 float*       __restrict__ out,
                 int M) {
    extern __shared__ float sm[];
    float* WT  = sm;
    float* acc = sm + SM_WT;

    int tid = threadIdx.x;

    // Stage W transposed+padded into smem: WT[k][f][c], row stride 36 floats (144B)
    for (int i = tid; i < 27 * 1024; i += 512) {
        int k = i >> 10;
        int rem = i & 1023;
        int c = rem >> 5;
        int f = rem & 31;
        WT[k * WT_TAP + f * WT_STRIDE + c] = W[i];
    }

    int warp = tid >> 5;
    int lane = tid & 31;
    float* accW = acc + warp * 1024;   // [32 rows][32 f]

    // zero per-warp accumulators (lane = feature column)
    #pragma unroll
    for (int r = 0; r < 32; r++) accW[r * 32 + lane] = 0.0f;
    __syncthreads();

    int rowBase = blockIdx.x * 512 + warp * 32;
    int myRow = rowBase + lane;
    bool myValid = myRow < M;
    int myLid = 0;
    if (myValid) {
        int x = out_pos[3 * myRow + 0];
        int y = out_pos[3 * myRow + 1];
        int z = out_pos[3 * myRow + 2];
        myLid = (x * GRIDL + y) * GRIDL + z;
    }

    // prefetch head for tap 0 (offset 0)
    int hcur = myValid ? __ldg(&g_head[myLid]) : 0;

    for (int k = 0; k < 27; k++) {
        // prefetch next tap's head before processing this tap
        int hnext = 0;
        if (k < 26) {
            int k1 = k + 1;
            int di = k1 / 9, rem9 = k1 - di * 9, dj = rem9 / 3, dk = rem9 - dj * 3;
            int off = di * (GRIDL * GRIDL) + dj * GRIDL + dk;
            hnext = myValid ? __ldg(&g_head[myLid + off]) : 0;
        }

        unsigned mask = __ballot_sync(0xffffffffu, hcur != 0);
        if (mask) {
            // hoist tap-k weight column for this lane's feature (as f32x2 pairs)
            const float* wt = WT + k * WT_TAP + lane * WT_STRIDE;
            F4U2 w0, w1, w2, w3, w4, w5, w6, w7;
            w0.f = *(const float4*)(wt + 0);
            w1.f = *(const float4*)(wt + 4);
            w2.f = *(const float4*)(wt + 8);
            w3.f = *(const float4*)(wt + 12);
            w4.f = *(const float4*)(wt + 16);
            w5.f = *(const float4*)(wt + 20);
            w6.f = *(const float4*)(wt + 24);
            w7.f = *(const float4*)(wt + 28);

            int head = hcur;
            while (mask) {
                int r = __ffs(mask) - 1;
                mask &= mask - 1;
                int p = __shfl_sync(0xffffffffu, head, r);
                unsigned long long aE = pack2(accW[r * 32 + lane], 0.0f);
                unsigned long long aO = 0ull;
                do {
                    int n = p - 1;
                    const float4* f4 = (const float4*)(feat + (size_t)n * 32);
                    F4U2 v;
                    v.f = __ldg(f4 + 0);
                    asm("fma.rn.f32x2 %0, %1, %2, %0;" : "+l"(aE) : "l"(v.u.x), "l"(w0.u.x));
                    asm("fma.rn.f32x2 %0, %1, %2, %0;" : "+l"(aO) : "l"(v.u.y), "l"(w0.u.y));
                    v.f = __ldg(f4 + 1);
                    asm("fma.rn.f32x2 %0, %1, %2, %0;" : "+l"(aE) : "l"(v.u.x), "l"(w1.u.x));
                    asm("fma.rn.f32x2 %0, %1, %2, %0;" : "+l"(aO) : "l"(v.u.y), "l"(w1.u.y));
                    v.f = __ldg(f4 + 2);
                    asm("fma.rn.f32x2 %0, %1, %2, %0;" : "+l"(aE) : "l"(v.u.x), "l"(w2.u.x));
                    asm("fma.rn.f32x2 %0, %1, %2, %0;" : "+l"(aO) : "l"(v.u.y), "l"(w2.u.y));
                    v.f = __ldg(f4 + 3);
                    asm("fma.rn.f32x2 %0, %1, %2, %0;" : "+l"(aE) : "l"(v.u.x), "l"(w3.u.x));
                    asm("fma.rn.f32x2 %0, %1, %2, %0;" : "+l"(aO) : "l"(v.u.y), "l"(w3.u.y));
                    v.f = __ldg(f4 + 4);
                    asm("fma.rn.f32x2 %0, %1, %2, %0;" : "+l"(aE) : "l"(v.u.x), "l"(w4.u.x));
                    asm("fma.rn.f32x2 %0, %1, %2, %0;" : "+l"(aO) : "l"(v.u.y), "l"(w4.u.y));
                    v.f = __ldg(f4 + 5);
                    asm("fma.rn.f32x2 %0, %1, %2, %0;" : "+l"(aE) : "l"(v.u.x), "l"(w5.u.x));
                    asm("fma.rn.f32x2 %0, %1, %2, %0;" : "+l"(aO) : "l"(v.u.y), "l"(w5.u.y));
                    v.f = __ldg(f4 + 6);
                    asm("fma.rn.f32x2 %0, %1, %2, %0;" : "+l"(aE) : "l"(v.u.x), "l"(w6.u.x));
                    asm("fma.rn.f32x2 %0, %1, %2, %0;" : "+l"(aO) : "l"(v.u.y), "l"(w6.u.y));
                    v.f = __ldg(f4 + 7);
                    asm("fma.rn.f32x2 %0, %1, %2, %0;" : "+l"(aE) : "l"(v.u.x), "l"(w7.u.x));
                    asm("fma.rn.f32x2 %0, %1, %2, %0;" : "+l"(aO) : "l"(v.u.y), "l"(w7.u.y));
                    p = __ldg(&g_next[n]);
                } while (p);
                float2 e = *reinterpret_cast<float2*>(&aE);
                float2 o = *reinterpret_cast<float2*>(&aO);
                accW[r * 32 + lane] = (e.x + e.y) + (o.x + o.y);
            }
        }
        hcur = hnext;
    }

    // write results (coalesced: 128B per row)
    #pragma unroll
    for (int r = 0; r < 32; r++) {
        int row = rowBase + r;
        if (row < M) out[row * 32 + lane] = accW[r * 32 + lane];
    }
}

extern "C" void kernel_launch(void* const* d_in, const int* in_sizes, int n_in,
                              void* d_out, int out_size) {
    const float* feat    = (const float*)d_in[0];
    const int*   in_pos  = (const int*)d_in[1];
    const int*   out_pos = (const int*)d_in[2];
    const float* W       = (const float*)d_in[3];
    float* out = (float*)d_out;

    int N = in_sizes[0] / 32;
    int M = in_sizes[2] / 3;

    cudaFuncSetAttribute(gather_conv, cudaFuncAttributeMaxDynamicSharedMemorySize, SMEM_BYTES);

    init_head<<<4096, 256>>>();
    build_chains<<<(N + 255) / 256, 256>>>(in_pos, N);
    gather_conv<<<(M + 511) / 512, 512, SMEM_BYTES>>>(feat, out_pos, W, out, M);
}